// round 13
// baseline (speedup 1.0000x reference)
#include <cuda_runtime.h>

#define FDIM 128
#define F4   32              // FDIM/4
#define BMAX 2048
#define NMAX 1100000
#define NCTA 148             // persistent sort CTAs (1/SM, single wave)
#define TILE 2048            // idx staging tile (rows)
#define NW   24              // warps per fused CTA (768 threads)
#define NT   768             // fused CTA threads
#define EPSC 1e-3f

// ---- scratch (device globals; no allocations allowed) ----
__device__ int g_gid32[NMAX];            // converted ids
__device__ int g_counts[BMAX];           // per-graph totals (atomic; reset by fused)
__device__ int g_offsets[BMAX + 1];      // per-graph base offsets
__device__ int g_perm[NMAX];             // node ids sorted by graph
__device__ int g_barrier[2];             // [0]=arrive counter, [1]=offsets-ready flag

// ---- persistent sort kernel: hist+atomic-prefix -> scan -> scatter ----
__global__ __launch_bounds__(512) void gn_sort_kernel(const void* __restrict__ gid,
                                                      int N, int B) {
    __shared__ int sh[BMAX];      // hist, then scatter cursors
    __shared__ int sbase[BMAX];   // this CTA's within-graph base
    __shared__ int part[512];
    __shared__ int s_is64;
    int t   = threadIdx.x;
    int cta = blockIdx.x;

    // ---- phase A: dtype probe + convert gid -> int32 + per-CTA histogram ----
    for (int i = t; i < B; i += 512) sh[i] = 0;
    if (t == 0) s_is64 = 1;
    __syncthreads();

    int chunk = (N + NCTA - 1) / NCTA;
    int s = cta * chunk;
    int e = s + chunk; if (e > N) e = N;

    {   // local probe: view chunk as int64; any out-of-range value -> int32
        int probe = (e - s) / 2;
        if (probe > 512) probe = 512;
        const long long* g64 = (const long long*)gid + (s / 2);
        if (t < probe) {
            long long v = g64[t];
            if (v < 0 || v >= (long long)B) s_is64 = 0;
        }
    }
    __syncthreads();
    int is64 = s_is64;

    for (int i = s + t; i < e; i += 512) {
        int g = is64 ? (int)((const long long*)gid)[i] : ((const int*)gid)[i];
        g = (g < 0) ? 0 : (g >= B ? B - 1 : g);
        g_gid32[i] = g;
        atomicAdd(&sh[g], 1);
    }
    __syncthreads();

    // within-graph base for this CTA via global atomic (order-free prefix)
    for (int i = t; i < B; i += 512) {
        int cnt = sh[i];
        sbase[i] = cnt ? atomicAdd(&g_counts[i], cnt) : 0;
    }

    // arrive: signal phase-A completion
    __syncthreads();
    __threadfence();
    if (t == 0) atomicAdd(&g_barrier[0], 1);

    // ---- phase B: CTA 0 waits for all, scans totals -> g_offsets, sets flag ----
    if (cta == 0) {
        if (t == 0) {
            while (atomicAdd(&g_barrier[0], 0) < NCTA) __nanosleep(64);
        }
        __syncthreads();
        for (int i = t; i < BMAX; i += 512) sh[i] = (i < B) ? __ldcg(&g_counts[i]) : 0;
        __syncthreads();
        int base = t * 4;                        // 512 thr x 4 = 2048
        int acc = 0;
#pragma unroll
        for (int j = 0; j < 4; j++) { int v = sh[base + j]; sh[base + j] = acc; acc += v; }
        part[t] = acc;
        __syncthreads();
        for (int off = 1; off < 512; off <<= 1) {
            int v = part[t];
            int add = (t >= off) ? part[t - off] : 0;
            __syncthreads();
            part[t] = v + add;
            __syncthreads();
        }
        int cb = (t > 0) ? part[t - 1] : 0;
#pragma unroll
        for (int j = 0; j < 4; j++)
            g_offsets[base + j] = sh[base + j] + cb;   // zeros beyond B => offsets[B]=N
        if (t == 511) g_offsets[BMAX] = part[511];
        __syncthreads();
        __threadfence();
        if (t == 0) atomicExch(&g_barrier[1], 1);      // publish offsets
    } else {
        if (t == 0) {
            while (atomicAdd(&g_barrier[1], 0) == 0) __nanosleep(64);
        }
        __syncthreads();
    }

    // ---- phase C: scatter with smem cursors (same chunk as phase A) ----
    for (int i = t; i < B; i += 512)
        sh[i] = __ldcg(&g_offsets[i]) + sbase[i];
    __syncthreads();
    for (int i = s + t; i < e; i += 512) {
        int g   = g_gid32[i];
        int pos = atomicAdd(&sh[g], 1);
        g_perm[pos] = i;
    }
}

// ---- FUSED stats + normalize. 1 CTA (768 thr / 24 warps) per graph,
// 2 CTAs/SM = 48 warps/SM (R11's parallelism) with only 296 concurrent
// graphs x 250KB = 74MB L2 working set (R10's residency) — the decoupled
// config. Regs forced <=42 by launch bounds (simple loop, no unroll; R11
// showed this compiles to 40 regs spill-free). loop2 __ldcs re-reads from
// L2, __stcs streaming stores avoid write-allocate pollution. Resets sort
// scratch for the next replay (stream-ordered).
__global__ __launch_bounds__(NT, 2) void gn_fused_kernel(const float* __restrict__ values,
                                                         const float* __restrict__ gamma,
                                                         const float* __restrict__ beta,
                                                         const float* __restrict__ alpha,
                                                         float* __restrict__ out,
                                                         int B) {
    __shared__ int   idx[TILE];
    __shared__ float ss[NW * FDIM];   // per-warp partial sums
    __shared__ float sq[NW * FDIM];   // per-warp partial sumsq
    __shared__ float scs[FDIM];
    __shared__ float shs[FDIM];

    if (blockIdx.x == 0) {            // reset sort scratch for next replay
        if (threadIdx.x < 2) g_barrier[threadIdx.x] = 0;
        for (int i = threadIdx.x; i < B; i += NT) g_counts[i] = 0;
    }

    int b     = blockIdx.x;
    int start = g_offsets[b];
    int end   = g_offsets[b + 1];
    int c     = end - start;
    if (c == 0) return;                 // uniform per CTA

    int w    = threadIdx.x >> 5;        // 0..23
    int lane = threadIdx.x & 31;

    const float4* v4 = (const float4*)values;
    float4*       o4 = (float4*)out;

    float4 s = make_float4(0.f, 0.f, 0.f, 0.f);
    float4 q = make_float4(0.f, 0.f, 0.f, 0.f);

    // ---- loop1: gather + moments ----
    for (int ts = start; ts < end; ts += TILE) {
        int tn = end - ts; if (tn > TILE) tn = TILE;
        __syncthreads();
        for (int i = threadIdx.x; i < tn; i += NT) idx[i] = g_perm[ts + i];
        __syncthreads();
        for (int r = w; r < tn; r += NW) {
            float4 v = __ldg(&v4[(size_t)idx[r] * F4 + lane]);
            s.x += v.x; s.y += v.y; s.z += v.z; s.w += v.w;
            q.x = fmaf(v.x, v.x, q.x);
            q.y = fmaf(v.y, v.y, q.y);
            q.z = fmaf(v.z, v.z, q.z);
            q.w = fmaf(v.w, v.w, q.w);
        }
    }

    ((float4*)ss)[w * F4 + lane] = s;
    ((float4*)sq)[w * F4 + lane] = q;
    __syncthreads();

    // ---- reduce NW partials, compute scale/shift ----
    int f = threadIdx.x;
    if (f < FDIM) {
        float S = 0.f, Q = 0.f;
#pragma unroll
        for (int i = 0; i < NW; i++) {
            S += ss[i * FDIM + f];
            Q += sq[i * FDIM + f];
        }
        float inv  = 1.0f / (float)c;
        float m    = S * inv;
        float m2   = Q * inv;
        float msh  = m * alpha[f];                    // shifted mean
        float var  = m2 - 2.0f * msh * m + msh * msh; // E[(x - msh)^2]
        float rstd = rsqrtf(var + EPSC);
        float sc   = gamma[f] * rstd;
        scs[f] = sc;
        shs[f] = beta[f] - msh * sc;
    }
    __syncthreads();

    float4 sc4 = ((const float4*)scs)[lane];
    float4 sh4 = ((const float4*)shs)[lane];

    // ---- loop2: normalize. Reads: L2 hits, evict-on-use. Writes: streaming. ----
    for (int ts = start; ts < end; ts += TILE) {
        int tn = end - ts; if (tn > TILE) tn = TILE;
        if (c > TILE) {                     // re-stage only if >1 tile
            __syncthreads();
            for (int i = threadIdx.x; i < tn; i += NT) idx[i] = g_perm[ts + i];
            __syncthreads();
        }
        for (int r = w; r < tn; r += NW) {
            size_t gi = (size_t)idx[r] * F4 + lane;
            float4 v  = __ldcs(&v4[gi]);
            float4 o;
            o.x = fmaf(v.x, sc4.x, sh4.x);
            o.y = fmaf(v.y, sc4.y, sh4.y);
            o.z = fmaf(v.z, sc4.z, sh4.z);
            o.w = fmaf(v.w, sc4.w, sh4.w);
            __stcs(&o4[gi], o);
        }
    }
}

extern "C" void kernel_launch(void* const* d_in, const int* in_sizes, int n_in,
                              void* d_out, int out_size) {
    const float* values = (const float*)d_in[0];
    const void*  gid    = d_in[1];
    // d_in[2] = reference_ids (only its length B is needed)
    const float* gamma  = (const float*)d_in[3];
    const float* beta   = (const float*)d_in[4];
    const float* alpha  = (const float*)d_in[5];

    int N = in_sizes[0] / FDIM;
    int B = in_sizes[2];
    if (B > BMAX) B = BMAX;
    if (B < 1)    B = 1;

    gn_sort_kernel<<<NCTA, 512>>>(gid, N, B);
    gn_fused_kernel<<<B, NT>>>(values, gamma, beta, alpha, (float*)d_out, B);
}

// round 14
// speedup vs baseline: 1.0047x; 1.0047x over previous
#include <cuda_runtime.h>

#define FDIM 128
#define F4   32              // FDIM/4
#define BMAX 2048
#define NMAX 1100000
#define NCTA 148             // persistent sort CTAs (1/SM, single wave)
#define TILE 2048            // idx staging tile (rows)
#define NW   16              // warps per fused CTA
#define GMAX 8               // max nodes per sort thread (148*1024*8 > NMAX)
#define EPSC 1e-3f

// ---- scratch (device globals; no allocations allowed) ----
__device__ int g_counts[BMAX];           // per-graph totals (atomic; reset by fused)
__device__ int g_offsets[BMAX + 1];      // per-graph base offsets
__device__ int g_perm[NMAX];             // node ids sorted by graph
__device__ int g_barrier[2];             // [0]=arrive counter, [1]=offsets-ready flag

// ---- persistent sort kernel: hist+atomic-prefix -> scan -> scatter ----
// 1024 threads; converted gids live in registers across the grid barrier
// (no g_gid32 round-trip: kills 8MB of traffic + the dependent-load chain).
__global__ __launch_bounds__(1024) void gn_sort_kernel(const void* __restrict__ gid,
                                                       int N, int B) {
    __shared__ int sh[BMAX];      // hist, then scatter cursors
    __shared__ int sbase[BMAX];   // this CTA's within-graph base
    __shared__ int part[1024];
    __shared__ int s_is64;
    int t   = threadIdx.x;
    int cta = blockIdx.x;

    // ---- phase A: dtype probe + convert + per-CTA histogram ----
    for (int i = t; i < B; i += 1024) sh[i] = 0;
    if (t == 0) s_is64 = 1;
    __syncthreads();

    int chunk = (N + NCTA - 1) / NCTA;
    int s = cta * chunk;
    int e = s + chunk; if (e > N) e = N;

    {   // local probe: view chunk as int64; any out-of-range value -> int32
        int probe = (e - s) / 2;
        if (probe > 1024) probe = 1024;
        const long long* g64 = (const long long*)gid + (s / 2);
        if (t < probe) {
            long long v = g64[t];
            if (v < 0 || v >= (long long)B) s_is64 = 0;
        }
    }
    __syncthreads();
    int is64 = s_is64;

    int gr[GMAX];                 // register-resident converted gids
#pragma unroll
    for (int it = 0; it < GMAX; it++) {
        int i = s + t + it * 1024;
        int g = -1;
        if (i < e) {
            g = is64 ? (int)((const long long*)gid)[i] : ((const int*)gid)[i];
            g = (g < 0) ? 0 : (g >= B ? B - 1 : g);
            atomicAdd(&sh[g], 1);
        }
        gr[it] = g;
    }
    __syncthreads();

    // within-graph base for this CTA via global atomic (order-free prefix)
    for (int i = t; i < B; i += 1024) {
        int cnt = sh[i];
        sbase[i] = cnt ? atomicAdd(&g_counts[i], cnt) : 0;
    }

    // arrive: signal phase-A completion
    __syncthreads();
    __threadfence();
    if (t == 0) atomicAdd(&g_barrier[0], 1);

    // ---- phase B: CTA 0 waits for all, scans totals -> g_offsets, sets flag ----
    if (cta == 0) {
        if (t == 0) {
            while (atomicAdd(&g_barrier[0], 0) < NCTA) __nanosleep(64);
        }
        __syncthreads();
        for (int i = t; i < BMAX; i += 1024) sh[i] = (i < B) ? __ldcg(&g_counts[i]) : 0;
        __syncthreads();
        int a = sh[2 * t];
        int bb = sh[2 * t + 1];
        part[t] = a + bb;
        __syncthreads();
        for (int off = 1; off < 1024; off <<= 1) {
            int v = part[t];
            int add = (t >= off) ? part[t - off] : 0;
            __syncthreads();
            part[t] = v + add;
            __syncthreads();
        }
        int excl = (t > 0) ? part[t - 1] : 0;
        g_offsets[2 * t]     = excl;           // zeros beyond B => offsets[B]=N
        g_offsets[2 * t + 1] = excl + a;
        if (t == 1023) g_offsets[BMAX] = part[1023];
        __syncthreads();
        __threadfence();
        if (t == 0) atomicExch(&g_barrier[1], 1);      // publish offsets
    } else {
        if (t == 0) {
            while (atomicAdd(&g_barrier[1], 0) == 0) __nanosleep(64);
        }
        __syncthreads();
    }

    // ---- phase C: scatter with smem cursors, gids from registers ----
    for (int i = t; i < B; i += 1024)
        sh[i] = __ldcg(&g_offsets[i]) + sbase[i];
    __syncthreads();
#pragma unroll
    for (int it = 0; it < GMAX; it++) {
        int i = s + t + it * 1024;
        int g = gr[it];
        if (g >= 0) {
            int pos = atomicAdd(&sh[g], 1);
            g_perm[pos] = i;
        }
    }
}

// ---- FUSED stats + normalize (R10/R12 committed config — converged).
// 1 CTA (512 thr / 16 warps) per graph, 2 CTAs/SM. loop1 __ldg populates L2
// (296 x 250KB = 74MB < 126MB); loop2 __ldcs re-reads from L2, __stcs
// streaming stores avoid write-allocate pollution. Resets sort scratch for
// the next replay (stream-ordered after the sort kernel finished).
__global__ __launch_bounds__(512, 2) void gn_fused_kernel(const float* __restrict__ values,
                                                          const float* __restrict__ gamma,
                                                          const float* __restrict__ beta,
                                                          const float* __restrict__ alpha,
                                                          float* __restrict__ out,
                                                          int B) {
    __shared__ int   idx[TILE];
    __shared__ float ss[NW * FDIM];   // per-warp partial sums
    __shared__ float sq[NW * FDIM];   // per-warp partial sumsq
    __shared__ float scs[FDIM];
    __shared__ float shs[FDIM];

    if (blockIdx.x == 0) {            // reset sort scratch for next replay
        if (threadIdx.x < 2) g_barrier[threadIdx.x] = 0;
        for (int i = threadIdx.x; i < B; i += 512) g_counts[i] = 0;
    }

    int b     = blockIdx.x;
    int start = g_offsets[b];
    int end   = g_offsets[b + 1];
    int c     = end - start;
    if (c == 0) return;                 // uniform per CTA

    int w    = threadIdx.x >> 5;        // 0..15
    int lane = threadIdx.x & 31;

    const float4* v4 = (const float4*)values;
    float4*       o4 = (float4*)out;

    float4 s = make_float4(0.f, 0.f, 0.f, 0.f);
    float4 q = make_float4(0.f, 0.f, 0.f, 0.f);

    // ---- loop1: gather + moments (2 independent rows in flight per warp) ----
    for (int ts = start; ts < end; ts += TILE) {
        int tn = end - ts; if (tn > TILE) tn = TILE;
        __syncthreads();
        for (int i = threadIdx.x; i < tn; i += 512) idx[i] = g_perm[ts + i];
        __syncthreads();
        int r = w;
        for (; r + NW < tn; r += 2 * NW) {
            float4 va = __ldg(&v4[(size_t)idx[r]      * F4 + lane]);
            float4 vb = __ldg(&v4[(size_t)idx[r + NW] * F4 + lane]);
            s.x += va.x; s.y += va.y; s.z += va.z; s.w += va.w;
            q.x = fmaf(va.x, va.x, q.x);
            q.y = fmaf(va.y, va.y, q.y);
            q.z = fmaf(va.z, va.z, q.z);
            q.w = fmaf(va.w, va.w, q.w);
            s.x += vb.x; s.y += vb.y; s.z += vb.z; s.w += vb.w;
            q.x = fmaf(vb.x, vb.x, q.x);
            q.y = fmaf(vb.y, vb.y, q.y);
            q.z = fmaf(vb.z, vb.z, q.z);
            q.w = fmaf(vb.w, vb.w, q.w);
        }
        if (r < tn) {
            float4 v = __ldg(&v4[(size_t)idx[r] * F4 + lane]);
            s.x += v.x; s.y += v.y; s.z += v.z; s.w += v.w;
            q.x = fmaf(v.x, v.x, q.x);
            q.y = fmaf(v.y, v.y, q.y);
            q.z = fmaf(v.z, v.z, q.z);
            q.w = fmaf(v.w, v.w, q.w);
        }
    }

    ((float4*)ss)[w * F4 + lane] = s;
    ((float4*)sq)[w * F4 + lane] = q;
    __syncthreads();

    // ---- reduce NW partials, compute scale/shift ----
    int f = threadIdx.x;
    if (f < FDIM) {
        float S = 0.f, Q = 0.f;
#pragma unroll
        for (int i = 0; i < NW; i++) {
            S += ss[i * FDIM + f];
            Q += sq[i * FDIM + f];
        }
        float inv  = 1.0f / (float)c;
        float m    = S * inv;
        float m2   = Q * inv;
        float msh  = m * alpha[f];                    // shifted mean
        float var  = m2 - 2.0f * msh * m + msh * msh; // E[(x - msh)^2]
        float rstd = rsqrtf(var + EPSC);
        float sc   = gamma[f] * rstd;
        scs[f] = sc;
        shs[f] = beta[f] - msh * sc;
    }
    __syncthreads();

    float4 sc4 = ((const float4*)scs)[lane];
    float4 sh4 = ((const float4*)shs)[lane];

    // ---- loop2: normalize. Reads: L2 hits, evict-on-use. Writes: streaming. ----
    for (int ts = start; ts < end; ts += TILE) {
        int tn = end - ts; if (tn > TILE) tn = TILE;
        if (c > TILE) {                     // re-stage only if >1 tile
            __syncthreads();
            for (int i = threadIdx.x; i < tn; i += 512) idx[i] = g_perm[ts + i];
            __syncthreads();
        }
        int r = w;
        for (; r + NW < tn; r += 2 * NW) {
            size_t ga = (size_t)idx[r]      * F4 + lane;
            size_t gb = (size_t)idx[r + NW] * F4 + lane;
            float4 va = __ldcs(&v4[ga]);
            float4 vb = __ldcs(&v4[gb]);
            float4 oa, ob;
            oa.x = fmaf(va.x, sc4.x, sh4.x);
            oa.y = fmaf(va.y, sc4.y, sh4.y);
            oa.z = fmaf(va.z, sc4.z, sh4.z);
            oa.w = fmaf(va.w, sc4.w, sh4.w);
            ob.x = fmaf(vb.x, sc4.x, sh4.x);
            ob.y = fmaf(vb.y, sc4.y, sh4.y);
            ob.z = fmaf(vb.z, sc4.z, sh4.z);
            ob.w = fmaf(vb.w, sc4.w, sh4.w);
            __stcs(&o4[ga], oa);
            __stcs(&o4[gb], ob);
        }
        if (r < tn) {
            size_t gi = (size_t)idx[r] * F4 + lane;
            float4 v  = __ldcs(&v4[gi]);
            float4 o;
            o.x = fmaf(v.x, sc4.x, sh4.x);
            o.y = fmaf(v.y, sc4.y, sh4.y);
            o.z = fmaf(v.z, sc4.z, sh4.z);
            o.w = fmaf(v.w, sc4.w, sh4.w);
            __stcs(&o4[gi], o);
        }
    }
}

extern "C" void kernel_launch(void* const* d_in, const int* in_sizes, int n_in,
                              void* d_out, int out_size) {
    const float* values = (const float*)d_in[0];
    const void*  gid    = d_in[1];
    // d_in[2] = reference_ids (only its length B is needed)
    const float* gamma  = (const float*)d_in[3];
    const float* beta   = (const float*)d_in[4];
    const float* alpha  = (const float*)d_in[5];

    int N = in_sizes[0] / FDIM;
    int B = in_sizes[2];
    if (B > BMAX) B = BMAX;
    if (B < 1)    B = 1;

    gn_sort_kernel<<<NCTA, 1024>>>(gid, N, B);
    gn_fused_kernel<<<B, 512>>>(values, gamma, beta, alpha, (float*)d_out, B);
}